// round 5
// baseline (speedup 1.0000x reference)
#include <cuda_runtime.h>
#include <cuda_fp16.h>

// ---------------------------------------------------------------------------
// out[4096,4096] = x @ sign(W) + b
// A = fp16(x), B = sign(W)^T fp16 (+-1 exact).
// mma.sync m16n8k16 with **fp16 accumulators** (full-rate HMMA), promoted to
// fp32 master accumulators every 2 k-iters (8 MMAs, k=128) => rel_err ~5e-4.
// ---------------------------------------------------------------------------

#define DIMM 4096

constexpr int BM = 128;
constexpr int BN = 128;
constexpr int BK = 64;
constexpr int STAGES = 3;
constexpr int KITERS = DIMM / BK;                 // 64
constexpr int TILE_BYTES = 128 * 64 * 2;          // 16384
constexpr int STAGE_BYTES = 2 * TILE_BYTES;       // 32768 (A + B)
constexpr int SMEM_TOTAL = STAGES * STAGE_BYTES;  // 98304

// Scratch (__device__ globals: allocation-free)
__device__ __align__(1024) __half g_ST[(size_t)DIMM * DIMM];  // [N][K] sign(W)^T fp16
__device__ __align__(1024) __half g_xh[(size_t)DIMM * DIMM];  // [M][K] fp16(x)

// ------------------------- helpers -----------------------------------------

__device__ __forceinline__ unsigned smem_u32(const void* p) {
    unsigned a;
    asm("{ .reg .u64 t; cvta.to.shared.u64 t, %1; cvt.u32.u64 %0, t; }" : "=r"(a) : "l"(p));
    return a;
}
__device__ __forceinline__ unsigned sw128(unsigned off) { return off ^ ((off >> 3) & 0x70); }

__device__ __forceinline__ void cp16(unsigned dst, const void* src) {
    asm volatile("cp.async.cg.shared.global [%0], [%1], 16;" ::"r"(dst), "l"(src));
}
__device__ __forceinline__ void ldsm_x4(unsigned& r0, unsigned& r1, unsigned& r2, unsigned& r3,
                                        unsigned addr) {
    asm volatile("ldmatrix.sync.aligned.m8n8.x4.shared.b16 {%0,%1,%2,%3}, [%4];"
                 : "=r"(r0), "=r"(r1), "=r"(r2), "=r"(r3)
                 : "r"(addr));
}
// fp16-accumulator HMMA (full rate)
__device__ __forceinline__ void mma_f16acc(unsigned* d, const unsigned* a, unsigned b0,
                                           unsigned b1) {
    asm volatile(
        "mma.sync.aligned.m16n8k16.row.col.f16.f16.f16.f16 "
        "{%0,%1}, {%2,%3,%4,%5}, {%6,%7}, {%0,%1};"
        : "+r"(d[0]), "+r"(d[1])
        : "r"(a[0]), "r"(a[1]), "r"(a[2]), "r"(a[3]), "r"(b0), "r"(b1));
}
// promote fp16x2 pair into 4 fp32 master accumulators, zero the fp16 acc
__device__ __forceinline__ void promote(float* f, unsigned* h) {
    __half2 v0 = *reinterpret_cast<__half2*>(&h[0]);
    __half2 v1 = *reinterpret_cast<__half2*>(&h[1]);
    float2 a = __half22float2(v0);
    float2 b = __half22float2(v1);
    f[0] += a.x; f[1] += a.y; f[2] += b.x; f[3] += b.y;
    h[0] = 0u; h[1] = 0u;
}

// ------------------------- prep (one kernel) --------------------------------
__global__ void prep_kernel(const float* __restrict__ x, const float* __restrict__ W) {
    __shared__ float t[32][33];
    int bid = blockIdx.x;
    int tid = threadIdx.x;
    if (bid < 16384) {
        size_t i = (size_t)bid * 1024 + tid * 4;
        float4 v = *reinterpret_cast<const float4*>(x + i);
        __half2* ph = reinterpret_cast<__half2*>(g_xh + i);
        ph[0] = __floats2half2_rn(v.x, v.y);
        ph[1] = __floats2half2_rn(v.z, v.w);
    } else {
        int b = bid - 16384;
        int nb = (b & 127) * 32, kb = (b >> 7) * 32;
        int tx = tid & 31, ty = tid >> 5;
#pragma unroll
        for (int i = 0; i < 4; i++) {
            float w = W[(size_t)(kb + ty + i * 8) * DIMM + nb + tx];
            t[ty + i * 8][tx] = (w > 0.f) ? 1.f : ((w < 0.f) ? -1.f : 0.f);
        }
        __syncthreads();
#pragma unroll
        for (int i = 0; i < 4; i++) {
            g_ST[(size_t)(nb + ty + i * 8) * DIMM + kb + tx] = __float2half(t[tx][ty + i * 8]);
        }
    }
}

// ------------------------- GEMM kernel -------------------------------------
// grid = 1024 CTAs; 256 threads (8 warps, 4m x 2n), warp tile 32x64, 2 CTAs/SM.
__global__ void __launch_bounds__(256, 2)
bgemm_kernel(const float* __restrict__ bias, float* __restrict__ out) {
    extern __shared__ char smem[];
    unsigned sb = smem_u32(smem);
    int tid = threadIdx.x;
    int wid = tid >> 5, lane = tid & 31;
    int wm = wid & 3;   // 0..3
    int wn = wid >> 2;  // 0..1
    int m_base = (blockIdx.x & 31) * BM;
    int n_base = (blockIdx.x >> 5) * BN;

    const char* gA = reinterpret_cast<const char*>(g_xh) + (size_t)m_base * (DIMM * 2);
    const char* gB = reinterpret_cast<const char*>(g_ST) + (size_t)n_base * (DIMM * 2);

    unsigned s_off[4];
    unsigned g_off[4];
#pragma unroll
    for (int p = 0; p < 4; p++) {
        int idx = p * 256 + tid;
        int row = idx >> 3, colb = (idx & 7) * 16;
        s_off[p] = sw128((unsigned)(row * 128 + colb));
        g_off[p] = (unsigned)(row * (DIMM * 2) + colb);
    }

#define LOAD_STAGE(s, kit)                                              \
    do {                                                                \
        unsigned base = sb + (s) * STAGE_BYTES;                         \
        unsigned kb = (unsigned)(kit) * (BK * 2);                       \
        _Pragma("unroll") for (int p = 0; p < 4; p++) {                 \
            cp16(base + s_off[p], gA + kb + g_off[p]);                  \
            cp16(base + TILE_BYTES + s_off[p], gB + kb + g_off[p]);     \
        }                                                               \
        asm volatile("cp.async.commit_group;");                         \
    } while (0)

    LOAD_STAGE(0, 0);
    LOAD_STAGE(1, 1);

    float accf[2][8][4];       // fp32 master
    unsigned acch[2][8][2];    // fp16 working (fp16x2 pairs)
#pragma unroll
    for (int mi = 0; mi < 2; mi++)
#pragma unroll
        for (int ni = 0; ni < 8; ni++) {
#pragma unroll
            for (int c = 0; c < 4; c++) accf[mi][ni][c] = 0.f;
            acch[mi][ni][0] = 0u;
            acch[mi][ni][1] = 0u;
        }

    int a_row = lane & 15;
    int a_colb = (lane >> 4) * 16;
    int b_row = ((lane >> 4) << 3) + (lane & 7);
    int b_colb = ((lane >> 3) & 1) * 16;

    int s = 0;
#pragma unroll 1
    for (int kit = 0; kit < KITERS; kit++) {
        if (kit + 1 < KITERS)
            asm volatile("cp.async.wait_group 1;" ::: "memory");
        else
            asm volatile("cp.async.wait_group 0;" ::: "memory");
        __syncthreads();

        if (kit + 2 < KITERS) LOAD_STAGE((s + 2) % STAGES, kit + 2);

        unsigned sA = sb + s * STAGE_BYTES;
        unsigned sB = sA + TILE_BYTES;

#pragma unroll
        for (int kt = 0; kt < 4; kt++) {
            unsigned a[2][4];
#pragma unroll
            for (int mi = 0; mi < 2; mi++) {
                int mrow = wm * 32 + mi * 16 + a_row;
                ldsm_x4(a[mi][0], a[mi][1], a[mi][2], a[mi][3],
                        sA + sw128((unsigned)(mrow * 128 + kt * 32 + a_colb)));
            }
#pragma unroll
            for (int nb = 0; nb < 4; nb++) {
                int nrow = wn * 64 + nb * 16 + b_row;
                unsigned r0, r1, r2, r3;
                ldsm_x4(r0, r1, r2, r3,
                        sB + sw128((unsigned)(nrow * 128 + kt * 32 + b_colb)));
                mma_f16acc(acch[0][2 * nb], a[0], r0, r1);
                mma_f16acc(acch[1][2 * nb], a[1], r0, r1);
                mma_f16acc(acch[0][2 * nb + 1], a[0], r2, r3);
                mma_f16acc(acch[1][2 * nb + 1], a[1], r2, r3);
            }
        }
        // promote fp16 working acc into fp32 every 2 k-iters (k=128 chunk)
        if (kit & 1) {
#pragma unroll
            for (int mi = 0; mi < 2; mi++)
#pragma unroll
                for (int ni = 0; ni < 8; ni++) promote(accf[mi][ni], acch[mi][ni]);
        }
        s = (s + 1) % STAGES;
    }

    // ------------------ epilogue ------------------
    int qrow = lane >> 2;
    int qcol = (lane & 3) * 2;
#pragma unroll
    for (int mi = 0; mi < 2; mi++) {
        int r0 = m_base + wm * 32 + mi * 16 + qrow;
#pragma unroll
        for (int ni = 0; ni < 8; ni++) {
            int c = n_base + wn * 64 + ni * 8 + qcol;
            float2 bb = *reinterpret_cast<const float2*>(bias + c);
            float2 v0, v1;
            v0.x = accf[mi][ni][0] + bb.x;
            v0.y = accf[mi][ni][1] + bb.y;
            v1.x = accf[mi][ni][2] + bb.x;
            v1.y = accf[mi][ni][3] + bb.y;
            *reinterpret_cast<float2*>(out + (size_t)r0 * DIMM + c) = v0;
            *reinterpret_cast<float2*>(out + (size_t)(r0 + 8) * DIMM + c) = v1;
        }
    }
#undef LOAD_STAGE
}

// ------------------------- launch ------------------------------------------

extern "C" void kernel_launch(void* const* d_in, const int* in_sizes, int n_in,
                              void* d_out, int out_size) {
    const float* x = (const float*)d_in[0];
    const float* W = (const float*)d_in[1];
    const float* b = (const float*)d_in[2];
    float* out = (float*)d_out;

    cudaFuncSetAttribute(bgemm_kernel, cudaFuncAttributeMaxDynamicSharedMemorySize, SMEM_TOTAL);

    prep_kernel<<<32768, 256>>>(x, W);
    bgemm_kernel<<<(DIMM / BM) * (DIMM / BN), 256, SMEM_TOTAL>>>(b, out);
}

// round 7
// speedup vs baseline: 1.0710x; 1.0710x over previous
#include <cuda_runtime.h>
#include <cuda_fp16.h>

// ---------------------------------------------------------------------------
// out[4096,4096] = x @ sign(W) + b
// A = fp16(x), B = sign(W)^T fp16 (+-1 exact), fp32 accumulators via
// mma.sync m16n8k16 (round-4 proven config), now with split-K=2:
// 2048 CTAs (6.92 waves, ~1% tail) reducing into out via red.global.add.f32.
// ---------------------------------------------------------------------------

#define DIMM 4096

constexpr int BM = 128;
constexpr int BN = 128;
constexpr int BK = 64;
constexpr int STAGES = 3;
constexpr int SPLITK = 2;
constexpr int KHALF = DIMM / SPLITK;              // 2048
constexpr int KITERS = KHALF / BK;                // 32
constexpr int TILE_BYTES = 128 * 64 * 2;          // 16384
constexpr int STAGE_BYTES = 2 * TILE_BYTES;       // 32768 (A + B)
constexpr int SMEM_TOTAL = STAGES * STAGE_BYTES;  // 98304

// Scratch (__device__ globals: allocation-free)
__device__ __align__(1024) __half g_ST[(size_t)DIMM * DIMM];  // [N][K] sign(W)^T fp16
__device__ __align__(1024) __half g_xh[(size_t)DIMM * DIMM];  // [M][K] fp16(x)

// ------------------------- helpers -----------------------------------------

__device__ __forceinline__ unsigned smem_u32(const void* p) {
    unsigned a;
    asm("{ .reg .u64 t; cvta.to.shared.u64 t, %1; cvt.u32.u64 %0, t; }" : "=r"(a) : "l"(p));
    return a;
}
__device__ __forceinline__ unsigned sw128(unsigned off) { return off ^ ((off >> 3) & 0x70); }

__device__ __forceinline__ void cp16(unsigned dst, const void* src) {
    asm volatile("cp.async.cg.shared.global [%0], [%1], 16;" ::"r"(dst), "l"(src));
}
__device__ __forceinline__ void ldsm_x4(unsigned& r0, unsigned& r1, unsigned& r2, unsigned& r3,
                                        unsigned addr) {
    asm volatile("ldmatrix.sync.aligned.m8n8.x4.shared.b16 {%0,%1,%2,%3}, [%4];"
                 : "=r"(r0), "=r"(r1), "=r"(r2), "=r"(r3)
                 : "r"(addr));
}
__device__ __forceinline__ void mma_f16(float* d, const unsigned* a, const unsigned* b) {
    asm volatile(
        "mma.sync.aligned.m16n8k16.row.col.f32.f16.f16.f32 "
        "{%0,%1,%2,%3}, {%4,%5,%6,%7}, {%8,%9}, {%0,%1,%2,%3};"
        : "+f"(d[0]), "+f"(d[1]), "+f"(d[2]), "+f"(d[3])
        : "r"(a[0]), "r"(a[1]), "r"(a[2]), "r"(a[3]), "r"(b[0]), "r"(b[1]));
}
__device__ __forceinline__ void red_add(float* addr, float v) {
    asm volatile("red.global.add.f32 [%0], %1;" ::"l"(addr), "f"(v) : "memory");
}

// ------------------------- prep (one kernel) --------------------------------
// blocks [0,16384): x -> fp16; blocks [16384,32768): W -> transposed sign fp16
__global__ void prep_kernel(const float* __restrict__ x, const float* __restrict__ W) {
    __shared__ float t[32][33];
    int bid = blockIdx.x;
    int tid = threadIdx.x;
    if (bid < 16384) {
        size_t i = (size_t)bid * 1024 + tid * 4;
        float4 v = *reinterpret_cast<const float4*>(x + i);
        __half2* ph = reinterpret_cast<__half2*>(g_xh + i);
        ph[0] = __floats2half2_rn(v.x, v.y);
        ph[1] = __floats2half2_rn(v.z, v.w);
    } else {
        int b = bid - 16384;
        int nb = (b & 127) * 32, kb = (b >> 7) * 32;
        int tx = tid & 31, ty = tid >> 5;
#pragma unroll
        for (int i = 0; i < 4; i++) {
            float w = W[(size_t)(kb + ty + i * 8) * DIMM + nb + tx];
            t[ty + i * 8][tx] = (w > 0.f) ? 1.f : ((w < 0.f) ? -1.f : 0.f);
        }
        __syncthreads();
#pragma unroll
        for (int i = 0; i < 4; i++) {
            g_ST[(size_t)(nb + ty + i * 8) * DIMM + kb + tx] = __float2half(t[tx][ty + i * 8]);
        }
    }
}

// ------------------------- GEMM kernel -------------------------------------
// grid = 2048 CTAs (32 mt x 32 nt x 2 kh); 256 threads (8 warps, 4m x 2n),
// warp tile 32x64; 2 CTAs/SM. Epilogue: red.global.add into zeroed out.
__global__ void __launch_bounds__(256, 2)
bgemm_kernel(const float* __restrict__ bias, float* __restrict__ out) {
    extern __shared__ char smem[];
    unsigned sb = smem_u32(smem);
    int tid = threadIdx.x;
    int wid = tid >> 5, lane = tid & 31;
    int wm = wid & 3;   // 0..3
    int wn = wid >> 2;  // 0..1
    int bid = blockIdx.x;
    int m_base = (bid & 31) * BM;
    int n_base = ((bid >> 5) & 31) * BN;
    int kh = bid >> 10;  // 0..1

    const char* gA = reinterpret_cast<const char*>(g_xh) + (size_t)m_base * (DIMM * 2) + (size_t)kh * (KHALF * 2);
    const char* gB = reinterpret_cast<const char*>(g_ST) + (size_t)n_base * (DIMM * 2) + (size_t)kh * (KHALF * 2);

    unsigned s_off[4];
    unsigned g_off[4];
#pragma unroll
    for (int p = 0; p < 4; p++) {
        int idx = p * 256 + tid;
        int row = idx >> 3, colb = (idx & 7) * 16;
        s_off[p] = sw128((unsigned)(row * 128 + colb));
        g_off[p] = (unsigned)(row * (DIMM * 2) + colb);
    }

#define LOAD_STAGE(s, kit)                                              \
    do {                                                                \
        unsigned base = sb + (s) * STAGE_BYTES;                         \
        unsigned kb = (unsigned)(kit) * (BK * 2);                       \
        _Pragma("unroll") for (int p = 0; p < 4; p++) {                 \
            cp16(base + s_off[p], gA + kb + g_off[p]);                  \
            cp16(base + TILE_BYTES + s_off[p], gB + kb + g_off[p]);     \
        }                                                               \
        asm volatile("cp.async.commit_group;");                         \
    } while (0)

    LOAD_STAGE(0, 0);
    LOAD_STAGE(1, 1);

    float acc[2][8][4];
#pragma unroll
    for (int mi = 0; mi < 2; mi++)
#pragma unroll
        for (int ni = 0; ni < 8; ni++)
#pragma unroll
            for (int c = 0; c < 4; c++) acc[mi][ni][c] = 0.f;

    int a_row = lane & 15;
    int a_colb = (lane >> 4) * 16;
    int b_row = ((lane >> 4) << 3) + (lane & 7);
    int b_colb = ((lane >> 3) & 1) * 16;

    int s = 0;
#pragma unroll 1
    for (int kit = 0; kit < KITERS; kit++) {
        if (kit + 1 < KITERS)
            asm volatile("cp.async.wait_group 1;" ::: "memory");
        else
            asm volatile("cp.async.wait_group 0;" ::: "memory");
        __syncthreads();

        if (kit + 2 < KITERS) LOAD_STAGE((s + 2) % STAGES, kit + 2);

        unsigned sA = sb + s * STAGE_BYTES;
        unsigned sB = sA + TILE_BYTES;

#pragma unroll
        for (int kt = 0; kt < 4; kt++) {
            unsigned bfr[8][2];
#pragma unroll
            for (int nb = 0; nb < 4; nb++) {
                int nrow = wn * 64 + nb * 16 + b_row;
                ldsm_x4(bfr[2 * nb][0], bfr[2 * nb][1], bfr[2 * nb + 1][0], bfr[2 * nb + 1][1],
                        sB + sw128((unsigned)(nrow * 128 + kt * 32 + b_colb)));
            }
            unsigned a[2][4];
#pragma unroll
            for (int mi = 0; mi < 2; mi++) {
                int mrow = wm * 32 + mi * 16 + a_row;
                ldsm_x4(a[mi][0], a[mi][1], a[mi][2], a[mi][3],
                        sA + sw128((unsigned)(mrow * 128 + kt * 32 + a_colb)));
            }
#pragma unroll
            for (int mi = 0; mi < 2; mi++)
#pragma unroll
                for (int ni = 0; ni < 8; ni++) mma_f16(acc[mi][ni], a[mi], bfr[ni]);
        }
        s = (s + 1) % STAGES;
    }

    // ------------------ epilogue: atomic reduce into out ------------------
    int qrow = lane >> 2;
    int qcol = (lane & 3) * 2;
#pragma unroll
    for (int mi = 0; mi < 2; mi++) {
        int r0 = m_base + wm * 32 + mi * 16 + qrow;
#pragma unroll
        for (int ni = 0; ni < 8; ni++) {
            int c = n_base + wn * 64 + ni * 8 + qcol;
            float b0 = 0.f, b1 = 0.f;
            if (kh == 0) {
                float2 bb = *reinterpret_cast<const float2*>(bias + c);
                b0 = bb.x;
                b1 = bb.y;
            }
            float* p0 = out + (size_t)r0 * DIMM + c;
            float* p1 = out + (size_t)(r0 + 8) * DIMM + c;
            red_add(p0, acc[mi][ni][0] + b0);
            red_add(p0 + 1, acc[mi][ni][1] + b1);
            red_add(p1, acc[mi][ni][2] + b0);
            red_add(p1 + 1, acc[mi][ni][3] + b1);
        }
    }
#undef LOAD_STAGE
}

// ------------------------- launch ------------------------------------------

extern "C" void kernel_launch(void* const* d_in, const int* in_sizes, int n_in,
                              void* d_out, int out_size) {
    const float* x = (const float*)d_in[0];
    const float* W = (const float*)d_in[1];
    const float* b = (const float*)d_in[2];
    float* out = (float*)d_out;

    cudaFuncSetAttribute(bgemm_kernel, cudaFuncAttributeMaxDynamicSharedMemorySize, SMEM_TOTAL);

    cudaMemsetAsync(out, 0, (size_t)out_size * sizeof(float));
    prep_kernel<<<32768, 256>>>(x, W);
    bgemm_kernel<<<32 * 32 * SPLITK, 256, SMEM_TOTAL>>>(b, out);
}

// round 10
// speedup vs baseline: 1.1989x; 1.1194x over previous
#include <cuda_runtime.h>
#include <cuda_fp16.h>

// ---------------------------------------------------------------------------
// out[4096,4096] = x @ sign(W) + b
// A = fp16(x), B = sign(W)^T fp16 (+-1 exact), fp32 acc, mma.sync m16n8k16.
// Mixed grid for tail elimination: 888 full-K tiles (= 3 x 296 slots) +
// 136 tiles split into 272 half-K CTAs that fill the last half-wave.
// Half-K CTAs reduce via red.global.add into a pre-zeroed 8.5MB region.
// ---------------------------------------------------------------------------

#define DIMM 4096

constexpr int BM = 128;
constexpr int BN = 128;
constexpr int BK = 64;
constexpr int STAGES = 3;
constexpr int TILE_BYTES = 128 * 64 * 2;          // 16384
constexpr int STAGE_BYTES = 2 * TILE_BYTES;       // 32768 (A + B)
constexpr int SMEM_TOTAL = STAGES * STAGE_BYTES;  // 98304

constexpr int FULL_TILES = 888;   // 3 * 296 (2 CTAs/SM * 148 SMs)
constexpr int HALF_TILES = 1024 - FULL_TILES;  // 136
constexpr int GRID = FULL_TILES + 2 * HALF_TILES;  // 1160

// Scratch (__device__ globals: allocation-free)
__device__ __align__(1024) __half g_ST[(size_t)DIMM * DIMM];  // [N][K] sign(W)^T fp16
__device__ __align__(1024) __half g_xh[(size_t)DIMM * DIMM];  // [M][K] fp16(x)

// ------------------------- helpers -----------------------------------------

__device__ __forceinline__ unsigned smem_u32(const void* p) {
    unsigned a;
    asm("{ .reg .u64 t; cvta.to.shared.u64 t, %1; cvt.u32.u64 %0, t; }" : "=r"(a) : "l"(p));
    return a;
}
__device__ __forceinline__ unsigned sw128(unsigned off) { return off ^ ((off >> 3) & 0x70); }

__device__ __forceinline__ void cp16(unsigned dst, const void* src) {
    asm volatile("cp.async.cg.shared.global [%0], [%1], 16;" ::"r"(dst), "l"(src));
}
__device__ __forceinline__ void ldsm_x4(unsigned& r0, unsigned& r1, unsigned& r2, unsigned& r3,
                                        unsigned addr) {
    asm volatile("ldmatrix.sync.aligned.m8n8.x4.shared.b16 {%0,%1,%2,%3}, [%4];"
                 : "=r"(r0), "=r"(r1), "=r"(r2), "=r"(r3)
                 : "r"(addr));
}
__device__ __forceinline__ void mma_f16(float* d, const unsigned* a, const unsigned* b) {
    asm volatile(
        "mma.sync.aligned.m16n8k16.row.col.f32.f16.f16.f32 "
        "{%0,%1,%2,%3}, {%4,%5,%6,%7}, {%8,%9}, {%0,%1,%2,%3};"
        : "+f"(d[0]), "+f"(d[1]), "+f"(d[2]), "+f"(d[3])
        : "r"(a[0]), "r"(a[1]), "r"(a[2]), "r"(a[3]), "r"(b[0]), "r"(b[1]));
}
__device__ __forceinline__ void red_add(float* addr, float v) {
    asm volatile("red.global.add.f32 [%0], %1;" ::"l"(addr), "f"(v) : "memory");
}

// ------------------------- prep (one kernel) --------------------------------
// blocks [0,16384): x -> fp16; blocks [16384,32768): W -> transposed sign fp16
__global__ void prep_kernel(const float* __restrict__ x, const float* __restrict__ W) {
    __shared__ float t[32][33];
    int bid = blockIdx.x;
    int tid = threadIdx.x;
    if (bid < 16384) {
        size_t i = (size_t)bid * 1024 + tid * 4;
        float4 v = *reinterpret_cast<const float4*>(x + i);
        __half2* ph = reinterpret_cast<__half2*>(g_xh + i);
        ph[0] = __floats2half2_rn(v.x, v.y);
        ph[1] = __floats2half2_rn(v.z, v.w);
    } else {
        int b = bid - 16384;
        int nb = (b & 127) * 32, kb = (b >> 7) * 32;
        int tx = tid & 31, ty = tid >> 5;
#pragma unroll
        for (int i = 0; i < 4; i++) {
            float w = W[(size_t)(kb + ty + i * 8) * DIMM + nb + tx];
            t[ty + i * 8][tx] = (w > 0.f) ? 1.f : ((w < 0.f) ? -1.f : 0.f);
        }
        __syncthreads();
#pragma unroll
        for (int i = 0; i < 4; i++) {
            g_ST[(size_t)(nb + ty + i * 8) * DIMM + kb + tx] = __float2half(t[tx][ty + i * 8]);
        }
    }
}

// Zero only the 136 split tiles' output regions (red.add targets).
// grid = HALF_TILES * 16 blocks, 256 threads, one float4 each.
__global__ void zero_kernel(float* __restrict__ out) {
    int b = blockIdx.x;
    int tile = FULL_TILES + (b >> 4);
    int f4i = (b & 15) * 256 + threadIdx.x;  // 0..4095 within tile
    int mt = tile & 31, nt = tile >> 5;
    int r = f4i >> 5, c4 = f4i & 31;
    float4* p = reinterpret_cast<float4*>(out) + (size_t)(mt * 128 + r) * 1024 + nt * 32 + c4;
    *p = make_float4(0.f, 0.f, 0.f, 0.f);
}

// ------------------------- GEMM kernel -------------------------------------
// grid = 1160 CTAs: bid<888 full-K tile; else half-K CTA pair per tile.
// 256 threads (8 warps, 4m x 2n), warp tile 32x64; 2 CTAs/SM.
__global__ void __launch_bounds__(256, 2)
bgemm_kernel(const float* __restrict__ bias, float* __restrict__ out) {
    extern __shared__ char smem[];
    unsigned sb = smem_u32(smem);
    int tid = threadIdx.x;
    int wid = tid >> 5, lane = tid & 31;
    int wm = wid & 3;   // 0..3
    int wn = wid >> 2;  // 0..1

    int bid = blockIdx.x;
    int tile, koff, nkits;
    bool full;
    if (bid < FULL_TILES) {
        tile = bid; koff = 0; nkits = 64; full = true;
    } else {
        int h = bid - FULL_TILES;
        tile = FULL_TILES + (h >> 1);
        koff = (h & 1) * 32;   // in kits
        nkits = 32;
        full = false;
    }
    int m_base = (tile & 31) * BM;
    int n_base = (tile >> 5) * BN;

    const char* gA = reinterpret_cast<const char*>(g_xh) + (size_t)m_base * (DIMM * 2) + (size_t)koff * (BK * 2);
    const char* gB = reinterpret_cast<const char*>(g_ST) + (size_t)n_base * (DIMM * 2) + (size_t)koff * (BK * 2);

    unsigned s_off[4];
    unsigned g_off[4];
#pragma unroll
    for (int p = 0; p < 4; p++) {
        int idx = p * 256 + tid;
        int row = idx >> 3, colb = (idx & 7) * 16;
        s_off[p] = sw128((unsigned)(row * 128 + colb));
        g_off[p] = (unsigned)(row * (DIMM * 2) + colb);
    }

#define LOAD_STAGE(s, kit)                                              \
    do {                                                                \
        unsigned base = sb + (s) * STAGE_BYTES;                         \
        unsigned kb = (unsigned)(kit) * (BK * 2);                       \
        _Pragma("unroll") for (int p = 0; p < 4; p++) {                 \
            cp16(base + s_off[p], gA + kb + g_off[p]);                  \
            cp16(base + TILE_BYTES + s_off[p], gB + kb + g_off[p]);     \
        }                                                               \
        asm volatile("cp.async.commit_group;");                         \
    } while (0)

    LOAD_STAGE(0, 0);
    LOAD_STAGE(1, 1);

    float acc[2][8][4];
#pragma unroll
    for (int mi = 0; mi < 2; mi++)
#pragma unroll
        for (int ni = 0; ni < 8; ni++)
#pragma unroll
            for (int c = 0; c < 4; c++) acc[mi][ni][c] = 0.f;

    int a_row = lane & 15;
    int a_colb = (lane >> 4) * 16;
    int b_row = ((lane >> 4) << 3) + (lane & 7);
    int b_colb = ((lane >> 3) & 1) * 16;

    int s = 0;
#pragma unroll 1
    for (int kit = 0; kit < nkits; kit++) {
        if (kit + 1 < nkits)
            asm volatile("cp.async.wait_group 1;" ::: "memory");
        else
            asm volatile("cp.async.wait_group 0;" ::: "memory");
        __syncthreads();

        unsigned sA = sb + s * STAGE_BYTES;
        unsigned sB = sA + TILE_BYTES;

#pragma unroll
        for (int kt = 0; kt < 4; kt++) {
            // defer next-stage cp.async until after kt0's work is issued:
            // cp.async and ldmatrix share LSU dispatch; MMAs start sooner.
            if (kt == 1 && kit + 2 < nkits) LOAD_STAGE((s + 2) % STAGES, kit + 2);

            unsigned bfr[8][2];
#pragma unroll
            for (int nb = 0; nb < 4; nb++) {
                int nrow = wn * 64 + nb * 16 + b_row;
                ldsm_x4(bfr[2 * nb][0], bfr[2 * nb][1], bfr[2 * nb + 1][0], bfr[2 * nb + 1][1],
                        sB + sw128((unsigned)(nrow * 128 + kt * 32 + b_colb)));
            }
            unsigned a[2][4];
#pragma unroll
            for (int mi = 0; mi < 2; mi++) {
                int mrow = wm * 32 + mi * 16 + a_row;
                ldsm_x4(a[mi][0], a[mi][1], a[mi][2], a[mi][3],
                        sA + sw128((unsigned)(mrow * 128 + kt * 32 + a_colb)));
            }
#pragma unroll
            for (int mi = 0; mi < 2; mi++)
#pragma unroll
                for (int ni = 0; ni < 8; ni++) mma_f16(acc[mi][ni], a[mi], bfr[ni]);
        }
        s = (s + 1) % STAGES;
    }

    // ------------------ epilogue ------------------
    int qrow = lane >> 2;
    int qcol = (lane & 3) * 2;
    if (full) {
#pragma unroll
        for (int mi = 0; mi < 2; mi++) {
            int r0 = m_base + wm * 32 + mi * 16 + qrow;
#pragma unroll
            for (int ni = 0; ni < 8; ni++) {
                int c = n_base + wn * 64 + ni * 8 + qcol;
                float2 bb = *reinterpret_cast<const float2*>(bias + c);
                float2 v0, v1;
                v0.x = acc[mi][ni][0] + bb.x;
                v0.y = acc[mi][ni][1] + bb.y;
                v1.x = acc[mi][ni][2] + bb.x;
                v1.y = acc[mi][ni][3] + bb.y;
                *reinterpret_cast<float2*>(out + (size_t)r0 * DIMM + c) = v0;
                *reinterpret_cast<float2*>(out + (size_t)(r0 + 8) * DIMM + c) = v1;
            }
        }
    } else {
#pragma unroll
        for (int mi = 0; mi < 2; mi++) {
            int r0 = m_base + wm * 32 + mi * 16 + qrow;
#pragma unroll
            for (int ni = 0; ni < 8; ni++) {
                int c = n_base + wn * 64 + ni * 8 + qcol;
                float b0 = 0.f, b1 = 0.f;
                if (koff == 0) {
                    float2 bb = *reinterpret_cast<const float2*>(bias + c);
                    b0 = bb.x;
                    b1 = bb.y;
                }
                float* p0 = out + (size_t)r0 * DIMM + c;
                float* p1 = out + (size_t)(r0 + 8) * DIMM + c;
                red_add(p0, acc[mi][ni][0] + b0);
                red_add(p0 + 1, acc[mi][ni][1] + b1);
                red_add(p1, acc[mi][ni][2] + b0);
                red_add(p1 + 1, acc[mi][ni][3] + b1);
            }
        }
    }
#undef LOAD_STAGE
}

// ------------------------- launch ------------------------------------------

extern "C" void kernel_launch(void* const* d_in, const int* in_sizes, int n_in,
                              void* d_out, int out_size) {
    const float* x = (const float*)d_in[0];
    const float* W = (const float*)d_in[1];
    const float* b = (const float*)d_in[2];
    float* out = (float*)d_out;

    cudaFuncSetAttribute(bgemm_kernel, cudaFuncAttributeMaxDynamicSharedMemorySize, SMEM_TOTAL);

    zero_kernel<<<HALF_TILES * 16, 256>>>(out);
    prep_kernel<<<32768, 256>>>(x, W);
    bgemm_kernel<<<GRID, 256, SMEM_TOTAL>>>(b, out);
}

// round 11
// speedup vs baseline: 1.2136x; 1.0122x over previous
#include <cuda_runtime.h>
#include <cuda_fp16.h>

// ---------------------------------------------------------------------------
// out[4096,4096] = x @ sign(W) + b
// A = fp16(x), B = sign(W)^T fp16 (+-1 exact), fp32 acc, mma.sync m16n8k16.
// Round-4 proven config + LSU de-burst micro-opts (deferred stage load,
// warp-skewed kt order) + faster prep stores.
// ---------------------------------------------------------------------------

#define DIMM 4096

constexpr int BM = 128;
constexpr int BN = 128;
constexpr int BK = 64;
constexpr int STAGES = 3;
constexpr int KITERS = DIMM / BK;                 // 64
constexpr int TILE_BYTES = 128 * 64 * 2;          // 16384
constexpr int STAGE_BYTES = 2 * TILE_BYTES;       // 32768 (A + B)
constexpr int SMEM_TOTAL = STAGES * STAGE_BYTES;  // 98304

// Scratch (__device__ globals: allocation-free)
__device__ __align__(1024) __half g_ST[(size_t)DIMM * DIMM];  // [N][K] sign(W)^T fp16
__device__ __align__(1024) __half g_xh[(size_t)DIMM * DIMM];  // [M][K] fp16(x)

// ------------------------- helpers -----------------------------------------

__device__ __forceinline__ unsigned smem_u32(const void* p) {
    unsigned a;
    asm("{ .reg .u64 t; cvta.to.shared.u64 t, %1; cvt.u32.u64 %0, t; }" : "=r"(a) : "l"(p));
    return a;
}
__device__ __forceinline__ unsigned sw128(unsigned off) { return off ^ ((off >> 3) & 0x70); }

__device__ __forceinline__ void cp16(unsigned dst, const void* src) {
    asm volatile("cp.async.cg.shared.global [%0], [%1], 16;" ::"r"(dst), "l"(src));
}
__device__ __forceinline__ void ldsm_x4(unsigned& r0, unsigned& r1, unsigned& r2, unsigned& r3,
                                        unsigned addr) {
    asm volatile("ldmatrix.sync.aligned.m8n8.x4.shared.b16 {%0,%1,%2,%3}, [%4];"
                 : "=r"(r0), "=r"(r1), "=r"(r2), "=r"(r3)
                 : "r"(addr));
}
__device__ __forceinline__ void mma_f16(float* d, const unsigned* a, const unsigned* b) {
    asm volatile(
        "mma.sync.aligned.m16n8k16.row.col.f32.f16.f16.f32 "
        "{%0,%1,%2,%3}, {%4,%5,%6,%7}, {%8,%9}, {%0,%1,%2,%3};"
        : "+f"(d[0]), "+f"(d[1]), "+f"(d[2]), "+f"(d[3])
        : "r"(a[0]), "r"(a[1]), "r"(a[2]), "r"(a[3]), "r"(b[0]), "r"(b[1]));
}

// ------------------------- prep (one kernel) --------------------------------
// blocks [0,8192): x -> fp16, 8 elems/thread (2x float4 in, 1x uint4 out)
// blocks [8192,24576): W -> transposed sign fp16 (32x32 tile per block)
__global__ void prep_kernel(const float* __restrict__ x, const float* __restrict__ W) {
    __shared__ float t[32][33];
    int bid = blockIdx.x;
    int tid = threadIdx.x;
    if (bid < 8192) {
        size_t i = (size_t)bid * 2048 + tid * 8;
        const float4* xv = reinterpret_cast<const float4*>(x + i);
        float4 v0 = xv[0];
        float4 v1 = xv[1];
        union { unsigned u[4]; uint4 q; } o;
        __half2 h;
        h = __floats2half2_rn(v0.x, v0.y); o.u[0] = *reinterpret_cast<unsigned*>(&h);
        h = __floats2half2_rn(v0.z, v0.w); o.u[1] = *reinterpret_cast<unsigned*>(&h);
        h = __floats2half2_rn(v1.x, v1.y); o.u[2] = *reinterpret_cast<unsigned*>(&h);
        h = __floats2half2_rn(v1.z, v1.w); o.u[3] = *reinterpret_cast<unsigned*>(&h);
        *reinterpret_cast<uint4*>(g_xh + i) = o.q;
    } else {
        int b = bid - 8192;
        int nb = (b & 127) * 32, kb = (b >> 7) * 32;
        int tx = tid & 31, ty = tid >> 5;
#pragma unroll
        for (int i = 0; i < 4; i++) {
            float w = W[(size_t)(kb + ty + i * 8) * DIMM + nb + tx];
            t[ty + i * 8][tx] = (w > 0.f) ? 1.f : ((w < 0.f) ? -1.f : 0.f);
        }
        __syncthreads();
#pragma unroll
        for (int i = 0; i < 4; i++) {
            g_ST[(size_t)(nb + ty + i * 8) * DIMM + kb + tx] = __float2half(t[tx][ty + i * 8]);
        }
    }
}

// ------------------------- GEMM kernel -------------------------------------
// grid = 1024 CTAs; 256 threads (8 warps, 4m x 2n), warp tile 32x64, 2 CTAs/SM.
__global__ void __launch_bounds__(256, 2)
bgemm_kernel(const float* __restrict__ bias, float* __restrict__ out) {
    extern __shared__ char smem[];
    unsigned sb = smem_u32(smem);
    int tid = threadIdx.x;
    int wid = tid >> 5, lane = tid & 31;
    int wm = wid & 3;   // 0..3
    int wn = wid >> 2;  // 0..1
    int m_base = (blockIdx.x & 31) * BM;
    int n_base = (blockIdx.x >> 5) * BN;

    const char* gA = reinterpret_cast<const char*>(g_xh) + (size_t)m_base * (DIMM * 2);
    const char* gB = reinterpret_cast<const char*>(g_ST) + (size_t)n_base * (DIMM * 2);

    unsigned s_off[4];
    unsigned g_off[4];
#pragma unroll
    for (int p = 0; p < 4; p++) {
        int idx = p * 256 + tid;
        int row = idx >> 3, colb = (idx & 7) * 16;
        s_off[p] = sw128((unsigned)(row * 128 + colb));
        g_off[p] = (unsigned)(row * (DIMM * 2) + colb);
    }

#define LOAD_STAGE(s, kit)                                              \
    do {                                                                \
        unsigned base = sb + (s) * STAGE_BYTES;                         \
        unsigned kb = (unsigned)(kit) * (BK * 2);                       \
        _Pragma("unroll") for (int p = 0; p < 4; p++) {                 \
            cp16(base + s_off[p], gA + kb + g_off[p]);                  \
            cp16(base + TILE_BYTES + s_off[p], gB + kb + g_off[p]);     \
        }                                                               \
        asm volatile("cp.async.commit_group;");                        \
    } while (0)

    LOAD_STAGE(0, 0);
    LOAD_STAGE(1, 1);

    float acc[2][8][4];
#pragma unroll
    for (int mi = 0; mi < 2; mi++)
#pragma unroll
        for (int ni = 0; ni < 8; ni++)
#pragma unroll
            for (int c = 0; c < 4; c++) acc[mi][ni][c] = 0.f;

    int a_row = lane & 15;
    int a_colb = (lane >> 4) * 16;
    int b_row = ((lane >> 4) << 3) + (lane & 7);
    int b_colb = ((lane >> 3) & 1) * 16;

    int s = 0;
#pragma unroll 1
    for (int kit = 0; kit < KITERS; kit++) {
        if (kit + 1 < KITERS)
            asm volatile("cp.async.wait_group 1;" ::: "memory");
        else
            asm volatile("cp.async.wait_group 0;" ::: "memory");
        __syncthreads();

        unsigned sA = sb + s * STAGE_BYTES;
        unsigned sB = sA + TILE_BYTES;

#pragma unroll
        for (int kt = 0; kt < 4; kt++) {
            // warp-skewed k-slice order: warps start on different slices so
            // the post-barrier ldsm burst is spread across the LSU.
            int kte = (kt + wid) & 3;

            // defer next-stage cp.async until after kt0's work is issued
            if (kt == 1 && kit + 2 < KITERS) LOAD_STAGE((s + 2) % STAGES, kit + 2);

            unsigned a[2][4];
#pragma unroll
            for (int mi = 0; mi < 2; mi++) {
                int mrow = wm * 32 + mi * 16 + a_row;
                ldsm_x4(a[mi][0], a[mi][1], a[mi][2], a[mi][3],
                        sA + sw128((unsigned)(mrow * 128 + kte * 32 + a_colb)));
            }
            unsigned bfr[8][2];
#pragma unroll
            for (int nb = 0; nb < 4; nb++) {
                int nrow = wn * 64 + nb * 16 + b_row;
                ldsm_x4(bfr[2 * nb][0], bfr[2 * nb][1], bfr[2 * nb + 1][0], bfr[2 * nb + 1][1],
                        sB + sw128((unsigned)(nrow * 128 + kte * 32 + b_colb)));
            }
#pragma unroll
            for (int mi = 0; mi < 2; mi++)
#pragma unroll
                for (int ni = 0; ni < 8; ni++) mma_f16(acc[mi][ni], a[mi], bfr[ni]);
        }
        s = (s + 1) % STAGES;
    }

    // ------------------ epilogue ------------------
    int qrow = lane >> 2;
    int qcol = (lane & 3) * 2;
#pragma unroll
    for (int mi = 0; mi < 2; mi++) {
        int r0 = m_base + wm * 32 + mi * 16 + qrow;
#pragma unroll
        for (int ni = 0; ni < 8; ni++) {
            int c = n_base + wn * 64 + ni * 8 + qcol;
            float2 bb = *reinterpret_cast<const float2*>(bias + c);
            float2 v0, v1;
            v0.x = acc[mi][ni][0] + bb.x;
            v0.y = acc[mi][ni][1] + bb.y;
            v1.x = acc[mi][ni][2] + bb.x;
            v1.y = acc[mi][ni][3] + bb.y;
            *reinterpret_cast<float2*>(out + (size_t)r0 * DIMM + c) = v0;
            *reinterpret_cast<float2*>(out + (size_t)(r0 + 8) * DIMM + c) = v1;
        }
    }
#undef LOAD_STAGE
}

// ------------------------- launch ------------------------------------------

extern "C" void kernel_launch(void* const* d_in, const int* in_sizes, int n_in,
                              void* d_out, int out_size) {
    const float* x = (const float*)d_in[0];
    const float* W = (const float*)d_in[1];
    const float* b = (const float*)d_in[2];
    float* out = (float*)d_out;

    cudaFuncSetAttribute(bgemm_kernel, cudaFuncAttributeMaxDynamicSharedMemorySize, SMEM_TOTAL);

    prep_kernel<<<24576, 256>>>(x, W);
    bgemm_kernel<<<(DIMM / BM) * (DIMM / BN), 256, SMEM_TOTAL>>>(b, out);
}